// round 3
// baseline (speedup 1.0000x reference)
#include <cuda_runtime.h>
#include <math.h>

// Problem dims
#define SS 512
#define BB 64
#define II 512
#define HH 1024
#define BH (BB*HH)

// Recurrent decomposition: 8 n-tiles (128 cols) x 16 k-chunks (64 k) = 128 blocks
#define NT 8
#define KC 16
#define NB (NT*KC)     // 128 persistent blocks (single wave)

// -------------------- device scratch (no cudaMalloc allowed) --------------------
__device__ float g_pre[SS*BH];        // V x_t + b_V + b_W
__device__ float g_part[KC][BH];      // split-K partials (4 MB)
__device__ unsigned g_arrive[NB];     // distributed barrier slots (monotonic tags)

// -------------------- packed f32x2 helpers --------------------------------------
typedef unsigned long long u64;

__device__ __forceinline__ u64 pack2(float x, float y) {
    u64 r; asm("mov.b64 %0, {%1, %2};" : "=l"(r) : "f"(x), "f"(y)); return r;
}
__device__ __forceinline__ u64 fma2(u64 a, u64 b, u64 c) {
    u64 d; asm("fma.rn.f32x2 %0, %1, %2, %3;" : "=l"(d) : "l"(a), "l"(b), "l"(c));
    return d;
}
__device__ __forceinline__ float2 unpack2(u64 v) {
    float2 f; asm("mov.b64 {%0, %1}, %2;" : "=f"(f.x), "=f"(f.y) : "l"(v)); return f;
}
__device__ __forceinline__ float tanh_fast(float x) {
    float y; asm("tanh.approx.f32 %0, %1;" : "=f"(y) : "f"(x)); return y;
}

// -------------------- distributed grid barrier -----------------------------------
// Arrive: one release-store of the current tag to this block's slot.
//   (st.release.gpu after __syncthreads orders ALL threads' prior STGs — the
//    same pattern cooperative-groups grid.sync uses.)
// Wait: threads 0..127 each acquire-poll one slot until it equals the tag.
// Tags increase 1..1024 within a launch; replays repeat the identical sequence,
// and the only barrier that can observe a stale cross-replay value (1024) is
// barrier tag=1, where 1024 != 1 -> correctly treated as not-arrived.
__device__ __forceinline__ void arrive_wait(int bid, int t, unsigned tag) {
    __syncthreads();
    if (t == 0) {
        asm volatile("st.release.gpu.global.b32 [%0], %1;"
                     :: "l"(g_arrive + bid), "r"(tag) : "memory");
    }
    if (t < NB) {
        unsigned v;
        do {
            asm volatile("ld.acquire.gpu.global.b32 %0, [%1];"
                         : "=r"(v) : "l"(g_arrive + t) : "memory");
        } while (v != tag);
    }
    __syncthreads();
}

// =================================================================================
// Kernel 1: g_pre[s,b,h] = sum_i x[s,b,i]*Vw[h,i] + Vb[h] + Wb[h]
// Tile 128x128, BK=16, 256 threads, 8x8 micro with f32x2 (crossbar-balanced).
// =================================================================================
__global__ void __launch_bounds__(256) pre_gemm_kernel(
        const float* __restrict__ x,
        const float* __restrict__ Vw,
        const float* __restrict__ Wb,
        const float* __restrict__ Vb) {
    __shared__ float As[128][20];
    __shared__ float Ws[16][132];

    const int bm = blockIdx.x;     // 0..255
    const int bn = blockIdx.y;     // 0..7
    const int t  = threadIdx.x;
    const int tx = t & 15;
    const int ty = t >> 4;

    u64 acc[8][4];
    #pragma unroll
    for (int j = 0; j < 8; j++)
        #pragma unroll
        for (int p = 0; p < 4; p++) acc[j][p] = 0ull;

    const float* Arow = x  + (size_t)(bm*128) * II;
    const float* Wrow = Vw + (size_t)(bn*128) * II;

    for (int kb = 0; kb < II; kb += 16) {
        #pragma unroll
        for (int it = 0; it < 2; it++) {
            int q  = t + it*256;
            int r  = q >> 2;
            int k4 = (q & 3) << 2;
            float4 va = *(const float4*)(Arow + (size_t)r*II + kb + k4);
            *(float4*)&As[r][k4] = va;
            float4 vw = *(const float4*)(Wrow + (size_t)r*II + kb + k4);
            Ws[k4+0][r] = vw.x; Ws[k4+1][r] = vw.y;
            Ws[k4+2][r] = vw.z; Ws[k4+3][r] = vw.w;
        }
        __syncthreads();
        #pragma unroll
        for (int k = 0; k < 16; k++) {
            ulonglong2 w01 = *(const ulonglong2*)&Ws[k][tx*8];
            ulonglong2 w23 = *(const ulonglong2*)&Ws[k][tx*8 + 4];
            #pragma unroll
            for (int j = 0; j < 8; j++) {
                float a = As[ty*8 + j][k];
                u64 ap = pack2(a, a);
                acc[j][0] = fma2(ap, w01.x, acc[j][0]);
                acc[j][1] = fma2(ap, w01.y, acc[j][1]);
                acc[j][2] = fma2(ap, w23.x, acc[j][2]);
                acc[j][3] = fma2(ap, w23.y, acc[j][3]);
            }
        }
        __syncthreads();
    }

    const int nbase = bn*128 + tx*8;
    float bias[8];
    #pragma unroll
    for (int i = 0; i < 8; i++) bias[i] = Vb[nbase+i] + Wb[nbase+i];

    #pragma unroll
    for (int j = 0; j < 8; j++) {
        size_t row = (size_t)bm*128 + ty*8 + j;
        float2 c0 = unpack2(acc[j][0]);
        float2 c1 = unpack2(acc[j][1]);
        float2 c2 = unpack2(acc[j][2]);
        float2 c3 = unpack2(acc[j][3]);
        float4 o0 = make_float4(c0.x+bias[0], c0.y+bias[1], c1.x+bias[2], c1.y+bias[3]);
        float4 o1 = make_float4(c2.x+bias[4], c2.y+bias[5], c3.x+bias[6], c3.y+bias[7]);
        *(float4*)&g_pre[row*HH + nbase]     = o0;
        *(float4*)&g_pre[row*HH + nbase + 4] = o1;
    }
}

// =================================================================================
// Kernel 2: persistent recurrence. 256 threads, 4(b)x8(n) micro, f32x2.
//   Block (nt,kc) keeps Ww[nt*128..+127][kc*64..+63] resident in SMEM.
//   Per step: phase A -> partials; barrier; phase B reduce+tanh -> h_t; barrier.
// =================================================================================
__global__ void __launch_bounds__(256) rnn_recurrent_kernel(
        const float* __restrict__ Ww,
        float* __restrict__ out) {
    extern __shared__ float smem[];
    float (*Ws)[132] = (float(*)[132])smem;               // [k=64][n=128+4]
    float (*As)[68]  = (float(*)[68])(smem + 64*132);     // [b=64][k=64+4]

    const int bid = blockIdx.x;
    const int nt  = bid & (NT-1);      // 0..7
    const int kc  = bid >> 3;          // 0..15
    const int t   = threadIdx.x;
    const int tx  = t & 15;            // n group: 16 x 8 = 128 cols
    const int ty  = t >> 4;            // b group: 16 x 4 =  64 rows

    // Preload resident Ww slice, transposed to [k][n]
    for (int q = t; q < 128*16; q += 256) {    // 128 n x 16 k4 float4s
        int n  = q >> 4;
        int k4 = (q & 15) << 2;
        float4 v = *(const float4*)(Ww + (size_t)(nt*128 + n)*HH + kc*64 + k4);
        Ws[k4+0][n] = v.x; Ws[k4+1][n] = v.y;
        Ws[k4+2][n] = v.z; Ws[k4+3][n] = v.w;
    }

    unsigned tag = 0;
    const int ob = (bid*256 + t)*2;    // phase B: one float2 per thread (128*256*2 = BH)

    for (int step = 0; step < SS; step++) {
        if (step > 0) {
            const float* hprev = out + (size_t)(step-1)*BH;
            // Stage h chunk [64 x 64] (produced by other SMs -> L2 path)
            for (int q = t; q < 64*16; q += 256) {
                int b  = q >> 4;
                int k4 = (q & 15) << 2;
                float4 v = __ldcg((const float4*)(hprev + (size_t)b*HH + kc*64 + k4));
                *(float4*)&As[b][k4] = v;
            }
            __syncthreads();

            u64 acc[4][4];
            #pragma unroll
            for (int j = 0; j < 4; j++)
                #pragma unroll
                for (int p = 0; p < 4; p++) acc[j][p] = 0ull;

            #pragma unroll 8
            for (int k = 0; k < 64; k++) {
                ulonglong2 w01 = *(const ulonglong2*)&Ws[k][tx*8];
                ulonglong2 w23 = *(const ulonglong2*)&Ws[k][tx*8 + 4];
                #pragma unroll
                for (int j = 0; j < 4; j++) {
                    float a = As[ty*4 + j][k];
                    u64 ap = pack2(a, a);
                    acc[j][0] = fma2(ap, w01.x, acc[j][0]);
                    acc[j][1] = fma2(ap, w01.y, acc[j][1]);
                    acc[j][2] = fma2(ap, w23.x, acc[j][2]);
                    acc[j][3] = fma2(ap, w23.y, acc[j][3]);
                }
            }
            #pragma unroll
            for (int j = 0; j < 4; j++) {
                float* dst = &g_part[kc][(size_t)(ty*4 + j)*HH + nt*128 + tx*8];
                ulonglong2 v0; v0.x = acc[j][0]; v0.y = acc[j][1];
                ulonglong2 v1; v1.x = acc[j][2]; v1.y = acc[j][3];
                *(ulonglong2*)(dst)     = v0;
                *(ulonglong2*)(dst + 4) = v1;
            }
        }

        // Prefetch pre-activation before waiting (independent of partials)
        float2 pre2 = *(const float2*)&g_pre[(size_t)step*BH + ob];

        tag++; arrive_wait(bid, t, tag);   // partials (all blocks) now visible

        // Phase B: reduce 16 partials + pre, tanh, write h_t (one float2/thread)
        {
            float2 a2 = pre2;
            if (step > 0) {
                #pragma unroll
                for (int kk = 0; kk < KC; kk++) {
                    float2 p = __ldcg((const float2*)&g_part[kk][ob]);
                    a2.x += p.x; a2.y += p.y;
                }
            }
            float2 h2;
            h2.x = tanh_fast(a2.x);
            h2.y = tanh_fast(a2.y);
            *(float2*)&out[(size_t)step*BH + ob] = h2;
        }

        tag++; arrive_wait(bid, t, tag);   // h_t (all blocks) now visible
    }

    // h_final copy: d_out[S*BH ..] = last hidden state
    {
        float2 v = __ldcg((const float2*)&out[(size_t)(SS-1)*BH + ob]);
        *(float2*)&out[(size_t)SS*BH + ob] = v;
    }
}

// =================================================================================
// Launch
// =================================================================================
extern "C" void kernel_launch(void* const* d_in, const int* in_sizes, int n_in,
                              void* d_out, int out_size) {
    const float* x  = (const float*)d_in[0];   // (S,B,I)
    const float* Ww = (const float*)d_in[1];   // (H,H)
    const float* Wb = (const float*)d_in[2];   // (H)
    const float* Vw = (const float*)d_in[3];   // (H,I)
    const float* Vb = (const float*)d_in[4];   // (H)
    float* out = (float*)d_out;                // (S,B,H) then (1,B,H)

    dim3 g1(256, 8);
    pre_gemm_kernel<<<g1, 256>>>(x, Vw, Wb, Vb);

    static int smem_set = 0;
    const int smem_bytes = (64*132 + 64*68) * (int)sizeof(float);  // 51200
    if (!smem_set) {
        cudaFuncSetAttribute(rnn_recurrent_kernel,
                             cudaFuncAttributeMaxDynamicSharedMemorySize, smem_bytes);
        smem_set = 1;
    }
    rnn_recurrent_kernel<<<NB, 256, smem_bytes>>>(Ww, out);
}

// round 4
// speedup vs baseline: 1.6091x; 1.6091x over previous
#include <cuda_runtime.h>
#include <math.h>

// Problem dims
#define SS 512
#define BB 64
#define II 512
#define HH 1024
#define BH (BB*HH)

// Recurrent decomposition: 32 n-tiles (32 cols, FULL K) x 4 batch-groups (16 rows)
#define NTILES 32
#define BGRP 4
#define NB (NTILES*BGRP)   // 128 persistent blocks, single wave, 1 barrier/step

// -------------------- device scratch (no cudaMalloc allowed) --------------------
__device__ float g_pre[SS*BH];        // V x_t + b_V + b_W
__device__ unsigned g_bar_cnt = 0;
__device__ volatile unsigned g_bar_gen = 0;

// -------------------- packed f32x2 helpers --------------------------------------
typedef unsigned long long u64;

__device__ __forceinline__ u64 pack2s(float x) {      // (x,x)
    u64 r; asm("mov.b64 %0, {%1, %1};" : "=l"(r) : "f"(x)); return r;
}
__device__ __forceinline__ u64 fma2(u64 a, u64 b, u64 c) {
    u64 d; asm("fma.rn.f32x2 %0, %1, %2, %3;" : "=l"(d) : "l"(a), "l"(b), "l"(c));
    return d;
}
__device__ __forceinline__ u64 add2(u64 a, u64 b) {
    u64 d; asm("add.rn.f32x2 %0, %1, %2;" : "=l"(d) : "l"(a), "l"(b)); return d;
}
__device__ __forceinline__ float2 unpack2(u64 v) {
    float2 f; asm("mov.b64 {%0, %1}, %2;" : "=f"(f.x), "=f"(f.y) : "l"(v)); return f;
}
__device__ __forceinline__ float tanh_fast(float x) {
    float y; asm("tanh.approx.f32 %0, %1;" : "=f"(y) : "f"(x)); return y;
}

// -------------------- grid barrier: ticket + generation broadcast ---------------
// (R1/R2-proven; single releaser, single spin address.)
__device__ __forceinline__ void grid_sync() {
    __syncthreads();
    __threadfence();                       // publish h STGs to L2 before arrival
    if (threadIdx.x == 0) {
        unsigned gen = g_bar_gen;
        if (atomicAdd(&g_bar_cnt, 1u) == NB - 1u) {
            g_bar_cnt = 0;
            __threadfence();
            g_bar_gen = gen + 1u;
        } else {
            while (g_bar_gen == gen) { }
        }
    }
    __syncthreads();
}

// =================================================================================
// Kernel 1: g_pre[s,b,h] = sum_i x[s,b,i]*Vw[h,i] + Vb[h] + Wb[h]
// Tile 128x128, BK=16, 256 threads, 8x8 micro with f32x2 (unchanged from R2).
// =================================================================================
__global__ void __launch_bounds__(256) pre_gemm_kernel(
        const float* __restrict__ x,
        const float* __restrict__ Vw,
        const float* __restrict__ Wb,
        const float* __restrict__ Vb) {
    __shared__ float As[128][20];
    __shared__ float Ws[16][132];

    const int bm = blockIdx.x;
    const int bn = blockIdx.y;
    const int t  = threadIdx.x;
    const int tx = t & 15;
    const int ty = t >> 4;

    u64 acc[8][4];
    #pragma unroll
    for (int j = 0; j < 8; j++)
        #pragma unroll
        for (int p = 0; p < 4; p++) acc[j][p] = 0ull;

    const float* Arow = x  + (size_t)(bm*128) * II;
    const float* Wrow = Vw + (size_t)(bn*128) * II;

    for (int kb = 0; kb < II; kb += 16) {
        #pragma unroll
        for (int it = 0; it < 2; it++) {
            int q  = t + it*256;
            int r  = q >> 2;
            int k4 = (q & 3) << 2;
            float4 va = *(const float4*)(Arow + (size_t)r*II + kb + k4);
            *(float4*)&As[r][k4] = va;
            float4 vw = *(const float4*)(Wrow + (size_t)r*II + kb + k4);
            Ws[k4+0][r] = vw.x; Ws[k4+1][r] = vw.y;
            Ws[k4+2][r] = vw.z; Ws[k4+3][r] = vw.w;
        }
        __syncthreads();
        #pragma unroll
        for (int k = 0; k < 16; k++) {
            ulonglong2 w01 = *(const ulonglong2*)&Ws[k][tx*8];
            ulonglong2 w23 = *(const ulonglong2*)&Ws[k][tx*8 + 4];
            #pragma unroll
            for (int j = 0; j < 8; j++) {
                u64 ap = pack2s(As[ty*8 + j][k]);
                acc[j][0] = fma2(ap, w01.x, acc[j][0]);
                acc[j][1] = fma2(ap, w01.y, acc[j][1]);
                acc[j][2] = fma2(ap, w23.x, acc[j][2]);
                acc[j][3] = fma2(ap, w23.y, acc[j][3]);
            }
        }
        __syncthreads();
    }

    const int nbase = bn*128 + tx*8;
    float bias[8];
    #pragma unroll
    for (int i = 0; i < 8; i++) bias[i] = Vb[nbase+i] + Wb[nbase+i];

    #pragma unroll
    for (int j = 0; j < 8; j++) {
        size_t row = (size_t)bm*128 + ty*8 + j;
        float2 c0 = unpack2(acc[j][0]);
        float2 c1 = unpack2(acc[j][1]);
        float2 c2 = unpack2(acc[j][2]);
        float2 c3 = unpack2(acc[j][3]);
        float4 o0 = make_float4(c0.x+bias[0], c0.y+bias[1], c1.x+bias[2], c1.y+bias[3]);
        float4 o1 = make_float4(c2.x+bias[4], c2.y+bias[5], c3.x+bias[6], c3.y+bias[7]);
        *(float4*)&g_pre[row*HH + nbase]     = o0;
        *(float4*)&g_pre[row*HH + nbase + 4] = o1;
    }
}

// =================================================================================
// Kernel 2: persistent recurrence, FULL-K sharding, ONE barrier per step.
//   Block (nt, bs): owns Ww[nt*32 .. +31][0..1023] resident in SMEM (128 KB),
//   computes h_t[bs*16 .. +15][nt*32 .. +31] = tanh( Ww_slice . h_{t-1} + pre ).
//   h_{t-1} rows staged through a 2-buffer SMEM pipeline (4 chunks of 256 k).
//   128 threads: tx = n-group (8 x 4 cols), ty = batch row (16).
// =================================================================================
#define CHUNK 256
#define ASPAD 260   // row pad to break bank alignment of 1KB rows

__global__ void __launch_bounds__(128) rnn_recurrent_kernel(
        const float* __restrict__ Ww,
        float* __restrict__ out) {
    extern __shared__ float smem[];
    float* Ws = smem;                       // [k=1024][n=32] flat: k*32+n (128 KB)
    float* As = smem + 1024*32;             // [buf=2][b=16][k=CHUNK] pad ASPAD

    const int bid = blockIdx.x;
    const int nt  = bid & (NTILES-1);       // 0..31
    const int bs  = bid >> 5;               // 0..3
    const int t   = threadIdx.x;
    const int tx  = t & 7;                  // n group (4 cols)
    const int ty  = t >> 3;                 // batch row 0..15

    const int orow = bs*16 + ty;
    const int ocol = nt*32 + tx*4;
    const size_t oOff = (size_t)orow*HH + ocol;

    // Preload resident Ww slice, transposed to [k][n]. q enumerates (k4, n).
    for (int q = t; q < 32*256; q += 128) {
        int n  = q & 31;
        int k4 = (q >> 5) << 2;
        float4 v = *(const float4*)(Ww + (size_t)(nt*32 + n)*HH + k4);
        Ws[(k4+0)*32 + n] = v.x;
        Ws[(k4+1)*32 + n] = v.y;
        Ws[(k4+2)*32 + n] = v.z;
        Ws[(k4+3)*32 + n] = v.w;
    }

    float4 hlast = make_float4(0.f, 0.f, 0.f, 0.f);

    for (int step = 0; step < SS; step++) {
        // Prefetch pre-activation early (independent of h)
        float4 pre4 = *(const float4*)&g_pre[(size_t)step*BH + oOff];

        float4 hv;
        if (step == 0) {
            hv = make_float4(tanh_fast(pre4.x), tanh_fast(pre4.y),
                             tanh_fast(pre4.z), tanh_fast(pre4.w));
        } else {
            const float* hbase = out + (size_t)(step-1)*BH + (size_t)(bs*16)*HH;

            float4 stg[8];
            // load chunk 0
            #pragma unroll
            for (int j = 0; j < 8; j++) {
                int idx = t + j*128;
                int b   = idx >> 6;
                int k4  = (idx & 63) << 2;
                stg[j] = __ldcg((const float4*)(hbase + (size_t)b*HH + k4));
            }
            #pragma unroll
            for (int j = 0; j < 8; j++) {
                int idx = t + j*128;
                int b   = idx >> 6;
                int k4  = (idx & 63) << 2;
                *(float4*)&As[(size_t)b*ASPAD + k4] = stg[j];
            }
            __syncthreads();

            u64 aA0 = 0ull, aA1 = 0ull, aB0 = 0ull, aB1 = 0ull;

            #pragma unroll 1
            for (int c = 0; c < 4; c++) {
                // prefetch next chunk into regs (in flight during compute)
                if (c < 3) {
                    #pragma unroll
                    for (int j = 0; j < 8; j++) {
                        int idx = t + j*128;
                        int b   = idx >> 6;
                        int k4  = (idx & 63) << 2;
                        stg[j] = __ldcg((const float4*)(hbase + (size_t)b*HH
                                                        + (c+1)*CHUNK + k4));
                    }
                }
                // compute on buf c&1
                const float* Arow = As + (size_t)((c & 1)*16 + ty)*ASPAD;
                const float* Wbase = Ws + (size_t)c*CHUNK*32 + tx*4;
                #pragma unroll 8
                for (int k = 0; k < CHUNK; k += 4) {
                    float4 a4 = *(const float4*)&Arow[k];
                    const float* wr = Wbase + (size_t)k*32;
                    ulonglong2 w0 = *(const ulonglong2*)(wr);
                    u64 ap0 = pack2s(a4.x);
                    aA0 = fma2(ap0, w0.x, aA0); aA1 = fma2(ap0, w0.y, aA1);
                    ulonglong2 w1 = *(const ulonglong2*)(wr + 32);
                    u64 ap1 = pack2s(a4.y);
                    aB0 = fma2(ap1, w1.x, aB0); aB1 = fma2(ap1, w1.y, aB1);
                    ulonglong2 w2 = *(const ulonglong2*)(wr + 64);
                    u64 ap2 = pack2s(a4.z);
                    aA0 = fma2(ap2, w2.x, aA0); aA1 = fma2(ap2, w2.y, aA1);
                    ulonglong2 w3 = *(const ulonglong2*)(wr + 96);
                    u64 ap3 = pack2s(a4.w);
                    aB0 = fma2(ap3, w3.x, aB0); aB1 = fma2(ap3, w3.y, aB1);
                }
                if (c < 3) {
                    __syncthreads();   // buf (c+1)&1 fully consumed (in iter c-1)
                    #pragma unroll
                    for (int j = 0; j < 8; j++) {
                        int idx = t + j*128;
                        int b   = idx >> 6;
                        int k4  = (idx & 63) << 2;
                        *(float4*)&As[(size_t)(((c+1)&1)*16 + b)*ASPAD + k4] = stg[j];
                    }
                    __syncthreads();
                }
            }

            u64 s0 = add2(aA0, aB0);
            u64 s1 = add2(aA1, aB1);
            float2 c01 = unpack2(s0);
            float2 c23 = unpack2(s1);
            hv = make_float4(tanh_fast(c01.x + pre4.x),
                             tanh_fast(c01.y + pre4.y),
                             tanh_fast(c23.x + pre4.z),
                             tanh_fast(c23.y + pre4.w));
        }

        *(float4*)&out[(size_t)step*BH + oOff] = hv;
        hlast = hv;

        if (step < SS-1) grid_sync();
    }

    // h_final: each thread wrote these exact elements — no barrier needed.
    *(float4*)&out[(size_t)SS*BH + oOff] = hlast;
}

// =================================================================================
// Launch
// =================================================================================
extern "C" void kernel_launch(void* const* d_in, const int* in_sizes, int n_in,
                              void* d_out, int out_size) {
    const float* x  = (const float*)d_in[0];   // (S,B,I)
    const float* Ww = (const float*)d_in[1];   // (H,H)
    const float* Wb = (const float*)d_in[2];   // (H)
    const float* Vw = (const float*)d_in[3];   // (H,I)
    const float* Vb = (const float*)d_in[4];   // (H)
    float* out = (float*)d_out;                // (S,B,H) then (1,B,H)

    dim3 g1(256, 8);
    pre_gemm_kernel<<<g1, 256>>>(x, Vw, Wb, Vb);

    static int smem_set = 0;
    const int smem_bytes = (1024*32 + 2*16*ASPAD) * (int)sizeof(float);  // 164352
    if (!smem_set) {
        cudaFuncSetAttribute(rnn_recurrent_kernel,
                             cudaFuncAttributeMaxDynamicSharedMemorySize, smem_bytes);
        smem_set = 1;
    }
    rnn_recurrent_kernel<<<NB, 128, smem_bytes>>>(Ww, out);
}